// round 9
// baseline (speedup 1.0000x reference)
#include <cuda_runtime.h>
#include <math.h>
#include <stdint.h>

// Problem constants
#define NBT    16384    // B * n_blocks (4 * 4096)
#define CDIM   256      // model channels
#define NB     4096     // blocks (tokens) per batch
#define BATCH  4
#define NLAYERS 4
#define KC320  320      // Eigen TensorContractionBlocking kc cap (min(..., 320))

// ---------------- scratch (device globals; no runtime allocation) ----------
__device__ float g_h [NBT * CDIM];
__device__ float g_hp[NBT * CDIM];
__device__ float g_k [NBT * CDIM];
__device__ float g_q [NBT * CDIM];
__device__ float g_v [NBT * CDIM];
__device__ float g_m [(size_t)BATCH * NB * NB];   // 268 MB score matrices

// ---------------------------------------------------------------------------
// XLA:CPU llvm_ir::EmitFastTanh, with_fma=true (aarch64 has FMA):
//   clamp to +-7.99881172180175781f  (the with_fma clamp constants!)
//   FMA-contracted Horner in x^2 (fast-math contraction -> fmla)
//   num = xc * P(x2); den = Q(x2); r = num/den (IEEE RN fdiv)
//   return |x| < 0.0004 ? x : r    (select on UNCLAMPED input)
// Op-for-op identical to the aarch64 codegen -> bitwise-matching outputs.
// ---------------------------------------------------------------------------
__device__ __forceinline__ float tanh_xla(float x)
{
    const float kClamp = 7.99881172180175781f;
    float xc = fminf(fmaxf(x, -kClamp), kClamp);
    float x2 = xc * xc;
    float p = -2.76076847742355e-16f;
    p = fmaf(x2, p,  2.00018790482477e-13f);
    p = fmaf(x2, p, -8.60467152213735e-11f);
    p = fmaf(x2, p,  5.12229709037114e-08f);
    p = fmaf(x2, p,  1.48572235717979e-05f);
    p = fmaf(x2, p,  6.37261928875436e-04f);
    p = fmaf(x2, p,  4.89352455891786e-03f);
    p = xc * p;
    float q = 1.19825839466702e-06f;
    q = fmaf(x2, q, 1.18534705686654e-04f);
    q = fmaf(x2, q, 2.26843463243900e-03f);
    q = fmaf(x2, q, 4.89352518554385e-03f);
    float r = __fdiv_rn(p, q);
    return (fabsf(x) < 0.0004f) ? x : r;
}

// Panel flush: tot += acc (RN add), acc = 0. Mirrors Eigen's per-kc-panel
// "C += panel" accumulation.
#define FLUSH_PANEL()                                  \
    do {                                               \
        _Pragma("unroll")                              \
        for (int i_ = 0; i_ < 4; i_++)                 \
            _Pragma("unroll")                          \
            for (int j_ = 0; j_ < 4; j_++) {           \
                tot[i_][j_] += acc[i_][j_];            \
                acc[i_][j_] = 0.f;                     \
            }                                          \
    } while (0)

// ---------------------------------------------------------------------------
// gemm_nt: C[m,n] = sum_k A[m,k] * B[n,k]   (A: MxK, B: NxK, row-major)
// Single ascending FFMA chain per element (K <= 320 -> one Eigen panel).
// ---------------------------------------------------------------------------
__global__ void __launch_bounds__(256)
gemm_nt(const float* __restrict__ A, const float* __restrict__ B,
        float* __restrict__ C, int M, int N, int K)
{
    __shared__ float As[16][64];
    __shared__ float Bs[16][64];

    const int bm = blockIdx.y * 64;
    const int bn = blockIdx.x * 64;
    const int tid = threadIdx.x;
    const int tx = tid & 15, ty = tid >> 4;
    const int lrow = tid >> 2;          // 0..63
    const int lcol = (tid & 3) << 2;    // 0,4,8,12

    float acc[4][4] = {};

    for (int k0 = 0; k0 < K; k0 += 16) {
        float4 a = *(const float4*)(A + (size_t)(bm + lrow) * K + k0 + lcol);
        float4 b = *(const float4*)(B + (size_t)(bn + lrow) * K + k0 + lcol);
        As[lcol+0][lrow] = a.x; As[lcol+1][lrow] = a.y;
        As[lcol+2][lrow] = a.z; As[lcol+3][lrow] = a.w;
        Bs[lcol+0][lrow] = b.x; Bs[lcol+1][lrow] = b.y;
        Bs[lcol+2][lrow] = b.z; Bs[lcol+3][lrow] = b.w;
        __syncthreads();
        #pragma unroll
        for (int kk = 0; kk < 16; kk++) {
            float4 av = *(const float4*)&As[kk][ty << 2];
            float4 bv = *(const float4*)&Bs[kk][tx << 2];
            float am[4] = {av.x, av.y, av.z, av.w};
            float bb[4] = {bv.x, bv.y, bv.z, bv.w};
            #pragma unroll
            for (int i = 0; i < 4; i++)
                #pragma unroll
                for (int j = 0; j < 4; j++)
                    acc[i][j] = fmaf(am[i], bb[j], acc[i][j]);
        }
        __syncthreads();
    }

    #pragma unroll
    for (int i = 0; i < 4; i++) {
        int m = bm + (ty << 2) + i;
        #pragma unroll
        for (int j = 0; j < 4; j++) {
            int n = bn + (tx << 2) + j;
            C[(size_t)m * N + n] = acc[i][j];
        }
    }
}

// ---------------------------------------------------------------------------
// scores: per batch b, M[t,s] = sum_c K[t,c] * Q[s,c], masked (t<s -> 0).
// K=256 <= 320 -> single panel. Upper-triangle-only tiles skipped.
// ---------------------------------------------------------------------------
__global__ void __launch_bounds__(256)
scores_kernel(const float* __restrict__ Kin, const float* __restrict__ Qin,
              float* __restrict__ Mout)
{
    const int bt = blockIdx.y * 64;   // t tile
    const int bs = blockIdx.x * 64;   // s tile
    if (bt + 63 < bs) return;         // fully upper triangle: unused

    const int b = blockIdx.z;
    const float* Kb = Kin + (size_t)b * NB * CDIM;
    const float* Qb = Qin + (size_t)b * NB * CDIM;
    float*       Mb = Mout + (size_t)b * NB * NB;

    __shared__ float As[16][64];
    __shared__ float Bs[16][64];

    const int tid = threadIdx.x;
    const int tx = tid & 15, ty = tid >> 4;
    const int lrow = tid >> 2;
    const int lcol = (tid & 3) << 2;

    float acc[4][4] = {};

    for (int k0 = 0; k0 < CDIM; k0 += 16) {
        float4 a  = *(const float4*)(Kb + (size_t)(bt + lrow) * CDIM + k0 + lcol);
        float4 b4 = *(const float4*)(Qb + (size_t)(bs + lrow) * CDIM + k0 + lcol);
        As[lcol+0][lrow] = a.x;  As[lcol+1][lrow] = a.y;
        As[lcol+2][lrow] = a.z;  As[lcol+3][lrow] = a.w;
        Bs[lcol+0][lrow] = b4.x; Bs[lcol+1][lrow] = b4.y;
        Bs[lcol+2][lrow] = b4.z; Bs[lcol+3][lrow] = b4.w;
        __syncthreads();
        #pragma unroll
        for (int kk = 0; kk < 16; kk++) {
            float4 av = *(const float4*)&As[kk][ty << 2];
            float4 bv = *(const float4*)&Bs[kk][tx << 2];
            float am[4] = {av.x, av.y, av.z, av.w};
            float bb[4] = {bv.x, bv.y, bv.z, bv.w};
            #pragma unroll
            for (int i = 0; i < 4; i++)
                #pragma unroll
                for (int j = 0; j < 4; j++)
                    acc[i][j] = fmaf(am[i], bb[j], acc[i][j]);
        }
        __syncthreads();
    }

    #pragma unroll
    for (int i = 0; i < 4; i++) {
        int t = bt + (ty << 2) + i;
        #pragma unroll
        for (int j = 0; j < 4; j++) {
            int s = bs + (tx << 2) + j;
            float val = acc[i][j];
            if (t < s) val = 0.f;     // tril: keep t >= s
            Mb[(size_t)t * NB + s] = val;
        }
    }
}

// ---------------------------------------------------------------------------
// av_tanh: per batch b, H[s,c] = tanh( sum_t M[t,s] * V[t,c] ).
// K=4096 -> Eigen kc=320 panels at ABSOLUTE t = 320*j: per-panel single
// ascending FMA chain, panels combined by RN adds (C += panel).
// Loop starts at the s-tile base: the skipped prefix is exact zeros (fma
// no-ops / +0.0 panel sums), bitwise identical to the full 0..NB chain.
// ---------------------------------------------------------------------------
__global__ void __launch_bounds__(256)
av_tanh_kernel(const float* __restrict__ Min, const float* __restrict__ Vin,
               float* __restrict__ Hout)
{
    const int b  = blockIdx.z;
    const int bs = blockIdx.y * 64;   // s tile (output rows)
    const int bc = blockIdx.x * 64;   // c tile (output cols)

    const float* Mb = Min + (size_t)b * NB * NB;
    const float* Vb = Vin + (size_t)b * NB * CDIM;
    float*       Hb = Hout + (size_t)b * NB * CDIM;

    __shared__ float As[16][64];   // M[t, s-local]
    __shared__ float Bs[16][64];   // V[t, c-local]

    const int tid = threadIdx.x;
    const int tx = tid & 15, ty = tid >> 4;
    const int row  = tid >> 4;          // t-local 0..15
    const int col4 = (tid & 15) << 2;   // 0..60

    float acc[4][4] = {};
    float tot[4][4] = {};
    int next_b = (bs / KC320 + 1) * KC320;   // first boundary strictly > bs

    for (int t0 = bs; t0 < NB; t0 += 16) {
        *(float4*)&As[row][col4] = *(const float4*)(Mb + (size_t)(t0 + row) * NB + bs + col4);
        *(float4*)&Bs[row][col4] = *(const float4*)(Vb + (size_t)(t0 + row) * CDIM + bc + col4);
        __syncthreads();
        const int bk = next_b - t0;   // boundary inside tile iff 0 <= bk < 16
        #pragma unroll
        for (int kk = 0; kk < 16; kk++) {
            if (kk == bk) FLUSH_PANEL();
            float4 av = *(const float4*)&As[kk][ty << 2];
            float4 bv = *(const float4*)&Bs[kk][tx << 2];
            float am[4] = {av.x, av.y, av.z, av.w};
            float bb[4] = {bv.x, bv.y, bv.z, bv.w};
            #pragma unroll
            for (int i = 0; i < 4; i++)
                #pragma unroll
                for (int j = 0; j < 4; j++)
                    acc[i][j] = fmaf(am[i], bb[j], acc[i][j]);
        }
        if (bk >= 0 && bk < 16) next_b += KC320;
        __syncthreads();
    }
    FLUSH_PANEL();

    #pragma unroll
    for (int i = 0; i < 4; i++) {
        int s = bs + (ty << 2) + i;
        #pragma unroll
        for (int j = 0; j < 4; j++) {
            int c = bc + (tx << 2) + j;
            Hb[(size_t)s * CDIM + c] = tanh_xla(tot[i][j]);
        }
    }
}

// ---------------------------------------------------------------------------
extern "C" void kernel_launch(void* const* d_in, const int* in_sizes, int n_in,
                              void* d_out, int out_size)
{
    const float* x     = (const float*)d_in[0];   // (4,1,524288)
    const float* W_in  = (const float*)d_in[1];   // (256,128)
    const float* Wp    = (const float*)d_in[2];   // (4,256,256)
    const float* Wk    = (const float*)d_in[3];
    const float* Wv    = (const float*)d_in[4];
    const float* Wq    = (const float*)d_in[5];
    const float* W_out = (const float*)d_in[6];   // (128,256)
    float* out = (float*)d_out;                   // (4,4096,128)

    float *h, *hp, *kb, *qb, *vb, *mm;
    cudaGetSymbolAddress((void**)&h,  g_h);
    cudaGetSymbolAddress((void**)&hp, g_hp);
    cudaGetSymbolAddress((void**)&kb, g_k);
    cudaGetSymbolAddress((void**)&qb, g_q);
    cudaGetSymbolAddress((void**)&vb, g_v);
    cudaGetSymbolAddress((void**)&mm, g_m);

    const dim3 blk(256);

    // Input projection: h = blocked_x @ W_in^T   (16384 x 256, K=128)
    gemm_nt<<<dim3(CDIM/64, NBT/64), blk>>>(x, W_in, h, NBT, CDIM, 128);

    for (int l = 0; l < NLAYERS; l++) {
        const float* wp = Wp + (size_t)l * CDIM * CDIM;
        const float* wk = Wk + (size_t)l * CDIM * CDIM;
        const float* wv = Wv + (size_t)l * CDIM * CDIM;
        const float* wq = Wq + (size_t)l * CDIM * CDIM;

        // hp = h @ wp^T ; K/Q/V = hp @ {wk,wq,wv}^T   (K=256: single panel)
        gemm_nt<<<dim3(4, NBT/64), blk>>>(h,  wp, hp, NBT, CDIM, CDIM);
        gemm_nt<<<dim3(4, NBT/64), blk>>>(hp, wk, kb, NBT, CDIM, CDIM);
        gemm_nt<<<dim3(4, NBT/64), blk>>>(hp, wq, qb, NBT, CDIM, CDIM);
        gemm_nt<<<dim3(4, NBT/64), blk>>>(hp, wv, vb, NBT, CDIM, CDIM);

        // M[t,s] = k_t . q_s, tril (per batch), K=256: single panel
        scores_kernel<<<dim3(NB/64, NB/64, BATCH), blk>>>(kb, qb, mm);

        // h[s,c] = tanh( sum_t M[t,s] V[t,c] ), K=4096: kc=320 panels
        av_tanh_kernel<<<dim3(CDIM/64, NB/64, BATCH), blk>>>(mm, vb, h);
    }

    // Output projection: out = h @ W_out^T   (16384 x 128, K=256)
    gemm_nt<<<dim3(2, NBT/64), blk>>>(h, W_out, out, NBT, 128, CDIM);
}

// round 10
// speedup vs baseline: 1.0070x; 1.0070x over previous
#include <cuda_runtime.h>
#include <math.h>
#include <stdint.h>

// Problem constants
#define NBT    16384    // B * n_blocks (4 * 4096)
#define CDIM   256      // model channels
#define NB     4096     // blocks (tokens) per batch
#define BATCH  4
#define NLAYERS 4
#define KC320  320      // Eigen TensorContractionBlocking kc cap

#define BK 16           // k-slice per smem stage
#define PAD 4           // smem row padding (keeps 16B alignment: 132*4=528)

typedef unsigned long long u64;

// ---------------- scratch (device globals; no runtime allocation) ----------
__device__ float g_h [NBT * CDIM];
__device__ float g_hp[NBT * CDIM];
__device__ float g_k [NBT * CDIM];
__device__ float g_q [NBT * CDIM];
__device__ float g_v [NBT * CDIM];
__device__ float g_m [(size_t)BATCH * NB * NB];   // 268 MB score matrices

// ---------------------------------------------------------------------------
// f32x2 packed helpers. fma.rn.f32x2 / add.rn.f32x2 perform two INDEPENDENT
// IEEE RN ops per instruction -> bitwise identical to scalar fmaf/__fadd_rn.
// ---------------------------------------------------------------------------
__device__ __forceinline__ u64 pack2(float lo, float hi)
{ u64 r; asm("mov.b64 %0, {%1,%2};" : "=l"(r) : "f"(lo), "f"(hi)); return r; }
__device__ __forceinline__ void unpack2(u64 v, float& lo, float& hi)
{ asm("mov.b64 {%0,%1}, %2;" : "=f"(lo), "=f"(hi) : "l"(v)); }
__device__ __forceinline__ u64 fma2(u64 a, u64 b, u64 c)
{ u64 d; asm("fma.rn.f32x2 %0, %1, %2, %3;" : "=l"(d) : "l"(a), "l"(b), "l"(c)); return d; }
__device__ __forceinline__ u64 add2(u64 a, u64 b)
{ u64 d; asm("add.rn.f32x2 %0, %1, %2;" : "=l"(d) : "l"(a), "l"(b)); return d; }

// ---------------------------------------------------------------------------
// XLA:CPU llvm_ir::EmitFastTanh, with_fma=true: clamp +-7.99881172180175781,
// FMA Horner, RN divide, |x|<4e-4 -> x (select on unclamped input).
// ---------------------------------------------------------------------------
__device__ __forceinline__ float tanh_xla(float x)
{
    const float kClamp = 7.99881172180175781f;
    float xc = fminf(fmaxf(x, -kClamp), kClamp);
    float x2 = xc * xc;
    float p = -2.76076847742355e-16f;
    p = fmaf(x2, p,  2.00018790482477e-13f);
    p = fmaf(x2, p, -8.60467152213735e-11f);
    p = fmaf(x2, p,  5.12229709037114e-08f);
    p = fmaf(x2, p,  1.48572235717979e-05f);
    p = fmaf(x2, p,  6.37261928875436e-04f);
    p = fmaf(x2, p,  4.89352455891786e-03f);
    p = xc * p;
    float q = 1.19825839466702e-06f;
    q = fmaf(x2, q, 1.18534705686654e-04f);
    q = fmaf(x2, q, 2.26843463243900e-03f);
    q = fmaf(x2, q, 4.89352518554385e-03f);
    float r = __fdiv_rn(p, q);
    return (fabsf(x) < 0.0004f) ? x : r;
}

// 8x8 microtile inner product step: a-broadcast (packed lo=hi), b pairs come
// directly from smem as ulonglong2. 32 FFMA2 = 64 scalar FMAs, each output
// element's chain unchanged (single accumulator, ascending k).
#define MICRO_STEP(AsRow, BsRow)                                          \
    do {                                                                  \
        float4 alo = *(const float4*)&(AsRow)[ty << 3];                   \
        float4 ahi = *(const float4*)&(AsRow)[(ty << 3) + 4];             \
        ulonglong2 blo = *(const ulonglong2*)&(BsRow)[tx << 3];           \
        ulonglong2 bhi = *(const ulonglong2*)&(BsRow)[(tx << 3) + 4];     \
        u64 b2[4] = {blo.x, blo.y, bhi.x, bhi.y};                         \
        float am[8] = {alo.x, alo.y, alo.z, alo.w,                        \
                       ahi.x, ahi.y, ahi.z, ahi.w};                       \
        _Pragma("unroll")                                                 \
        for (int i_ = 0; i_ < 8; i_++) {                                  \
            u64 a2 = pack2(am[i_], am[i_]);                               \
            _Pragma("unroll")                                             \
            for (int j_ = 0; j_ < 4; j_++)                                \
                acc2[i_][j_] = fma2(a2, b2[j_], acc2[i_][j_]);            \
        }                                                                 \
    } while (0)

// ---------------------------------------------------------------------------
// gemm_nt: C[m,n] = sum_k A[m,k] * B[n,k]   (A: MxK, B: NxK, row-major)
// 128x128 tile, 8x8 microtile, FFMA2. Single ascending chain (K <= 320).
// ---------------------------------------------------------------------------
__global__ void __launch_bounds__(256)
gemm_nt(const float* __restrict__ A, const float* __restrict__ B,
        float* __restrict__ C, int M, int N, int K)
{
    __shared__ float As[BK][128 + PAD];
    __shared__ float Bs[BK][128 + PAD];

    const int bm = blockIdx.y << 7;
    const int bn = blockIdx.x << 7;
    const int tid = threadIdx.x;
    const int tx = tid & 15, ty = tid >> 4;
    const int lrow = tid >> 2;          // 0..63
    const int lcol = (tid & 3) << 2;    // 0,4,8,12

    u64 acc2[8][4];
    #pragma unroll
    for (int i = 0; i < 8; i++)
        #pragma unroll
        for (int j = 0; j < 4; j++) acc2[i][j] = 0ull;

    for (int k0 = 0; k0 < K; k0 += BK) {
        float4 a0 = *(const float4*)(A + (size_t)(bm + lrow)      * K + k0 + lcol);
        float4 a1 = *(const float4*)(A + (size_t)(bm + lrow + 64) * K + k0 + lcol);
        float4 b0 = *(const float4*)(B + (size_t)(bn + lrow)      * K + k0 + lcol);
        float4 b1 = *(const float4*)(B + (size_t)(bn + lrow + 64) * K + k0 + lcol);
        As[lcol+0][lrow] = a0.x; As[lcol+1][lrow] = a0.y;
        As[lcol+2][lrow] = a0.z; As[lcol+3][lrow] = a0.w;
        As[lcol+0][lrow+64] = a1.x; As[lcol+1][lrow+64] = a1.y;
        As[lcol+2][lrow+64] = a1.z; As[lcol+3][lrow+64] = a1.w;
        Bs[lcol+0][lrow] = b0.x; Bs[lcol+1][lrow] = b0.y;
        Bs[lcol+2][lrow] = b0.z; Bs[lcol+3][lrow] = b0.w;
        Bs[lcol+0][lrow+64] = b1.x; Bs[lcol+1][lrow+64] = b1.y;
        Bs[lcol+2][lrow+64] = b1.z; Bs[lcol+3][lrow+64] = b1.w;
        __syncthreads();
        #pragma unroll
        for (int kk = 0; kk < BK; kk++) MICRO_STEP(As[kk], Bs[kk]);
        __syncthreads();
    }

    #pragma unroll
    for (int i = 0; i < 8; i++) {
        int m = bm + (ty << 3) + i;
        #pragma unroll
        for (int j = 0; j < 4; j++)
            *(u64*)(C + (size_t)m * N + bn + (tx << 3) + (j << 1)) = acc2[i][j];
    }
}

// ---------------------------------------------------------------------------
// scores: per batch b, M[t,s] = sum_c K[t,c] * Q[s,c], masked (t<s -> 0).
// 128x128 tiles; fully-upper tiles skipped (never read downstream).
// ---------------------------------------------------------------------------
__global__ void __launch_bounds__(256)
scores_kernel(const float* __restrict__ Kin, const float* __restrict__ Qin,
              float* __restrict__ Mout)
{
    const int bt = blockIdx.y << 7;   // t tile
    const int bs = blockIdx.x << 7;   // s tile
    if (bt + 127 < bs) return;        // fully upper triangle: unused

    const int b = blockIdx.z;
    const float* Kb = Kin + (size_t)b * NB * CDIM;
    const float* Qb = Qin + (size_t)b * NB * CDIM;
    float*       Mb = Mout + (size_t)b * NB * NB;

    __shared__ float As[BK][128 + PAD];
    __shared__ float Bs[BK][128 + PAD];

    const int tid = threadIdx.x;
    const int tx = tid & 15, ty = tid >> 4;
    const int lrow = tid >> 2;
    const int lcol = (tid & 3) << 2;

    u64 acc2[8][4];
    #pragma unroll
    for (int i = 0; i < 8; i++)
        #pragma unroll
        for (int j = 0; j < 4; j++) acc2[i][j] = 0ull;

    for (int k0 = 0; k0 < CDIM; k0 += BK) {
        float4 a0 = *(const float4*)(Kb + (size_t)(bt + lrow)      * CDIM + k0 + lcol);
        float4 a1 = *(const float4*)(Kb + (size_t)(bt + lrow + 64) * CDIM + k0 + lcol);
        float4 b0 = *(const float4*)(Qb + (size_t)(bs + lrow)      * CDIM + k0 + lcol);
        float4 b1 = *(const float4*)(Qb + (size_t)(bs + lrow + 64) * CDIM + k0 + lcol);
        As[lcol+0][lrow] = a0.x; As[lcol+1][lrow] = a0.y;
        As[lcol+2][lrow] = a0.z; As[lcol+3][lrow] = a0.w;
        As[lcol+0][lrow+64] = a1.x; As[lcol+1][lrow+64] = a1.y;
        As[lcol+2][lrow+64] = a1.z; As[lcol+3][lrow+64] = a1.w;
        Bs[lcol+0][lrow] = b0.x; Bs[lcol+1][lrow] = b0.y;
        Bs[lcol+2][lrow] = b0.z; Bs[lcol+3][lrow] = b0.w;
        Bs[lcol+0][lrow+64] = b1.x; Bs[lcol+1][lrow+64] = b1.y;
        Bs[lcol+2][lrow+64] = b1.z; Bs[lcol+3][lrow+64] = b1.w;
        __syncthreads();
        #pragma unroll
        for (int kk = 0; kk < BK; kk++) MICRO_STEP(As[kk], Bs[kk]);
        __syncthreads();
    }

    #pragma unroll
    for (int i = 0; i < 8; i++) {
        int t = bt + (ty << 3) + i;
        #pragma unroll
        for (int j = 0; j < 4; j++) {
            int s = bs + (tx << 3) + (j << 1);
            float lo, hi; unpack2(acc2[i][j], lo, hi);
            Mb[(size_t)t * NB + s]     = (t < s)     ? 0.f : lo;
            Mb[(size_t)t * NB + s + 1] = (t < s + 1) ? 0.f : hi;
        }
    }
}

// ---------------------------------------------------------------------------
// av_tanh: per batch b, H[s,c] = tanh( sum_t M[t,s] * V[t,c] ).
// 128s x 128c tile. Eigen kc=320 panels at ABSOLUTE t=320*j (320%16==0 so
// boundaries align with chunk starts: flush when t0%320==0 -- at t0==bs this
// is a no-op on all-zero accumulators, bitwise harmless). Loop starts at the
// s-tile base: skipped prefix is exact zeros (fma no-ops / +0.0 panel sums),
// bitwise identical to the full 0..NB Eigen chain.
// ---------------------------------------------------------------------------
__global__ void __launch_bounds__(256)
av_tanh_kernel(const float* __restrict__ Min, const float* __restrict__ Vin,
               float* __restrict__ Hout)
{
    const int b  = blockIdx.z;
    const int bs = blockIdx.y << 7;   // s tile (output rows)
    const int bc = blockIdx.x << 7;   // c tile (output cols)

    const float* Mb = Min + (size_t)b * NB * NB;
    const float* Vb = Vin + (size_t)b * NB * CDIM;
    float*       Hb = Hout + (size_t)b * NB * CDIM;

    __shared__ float Ms[BK][128 + PAD];   // M[t, s-local]
    __shared__ float Vs[BK][128 + PAD];   // V[t, c-local]

    const int tid = threadIdx.x;
    const int tx = tid & 15, ty = tid >> 4;
    const int trow  = tid >> 4;          // t-local 0..15
    const int tcol4 = (tid & 15) << 2;   // 0..60

    u64 acc2[8][4], tot2[8][4];
    #pragma unroll
    for (int i = 0; i < 8; i++)
        #pragma unroll
        for (int j = 0; j < 4; j++) { acc2[i][j] = 0ull; tot2[i][j] = 0ull; }

    for (int t0 = bs; t0 < NB; t0 += BK) {
        if ((t0 % KC320) == 0) {          // Eigen panel boundary (aligned)
            #pragma unroll
            for (int i = 0; i < 8; i++)
                #pragma unroll
                for (int j = 0; j < 4; j++) {
                    tot2[i][j] = add2(tot2[i][j], acc2[i][j]);
                    acc2[i][j] = 0ull;
                }
        }
        const float* Mrow = Mb + (size_t)(t0 + trow) * NB + bs;
        const float* Vrow = Vb + (size_t)(t0 + trow) * CDIM + bc;
        *(float4*)&Ms[trow][tcol4]      = *(const float4*)(Mrow + tcol4);
        *(float4*)&Ms[trow][tcol4 + 64] = *(const float4*)(Mrow + tcol4 + 64);
        *(float4*)&Vs[trow][tcol4]      = *(const float4*)(Vrow + tcol4);
        *(float4*)&Vs[trow][tcol4 + 64] = *(const float4*)(Vrow + tcol4 + 64);
        __syncthreads();
        #pragma unroll
        for (int kk = 0; kk < BK; kk++) MICRO_STEP(Ms[kk], Vs[kk]);
        __syncthreads();
    }
    #pragma unroll
    for (int i = 0; i < 8; i++)
        #pragma unroll
        for (int j = 0; j < 4; j++)
            tot2[i][j] = add2(tot2[i][j], acc2[i][j]);

    #pragma unroll
    for (int i = 0; i < 8; i++) {
        int s = bs + (ty << 3) + i;
        #pragma unroll
        for (int j = 0; j < 4; j++) {
            int c = bc + (tx << 3) + (j << 1);
            float lo, hi; unpack2(tot2[i][j], lo, hi);
            Hb[(size_t)s * CDIM + c]     = tanh_xla(lo);
            Hb[(size_t)s * CDIM + c + 1] = tanh_xla(hi);
        }
    }
}

// ---------------------------------------------------------------------------
extern "C" void kernel_launch(void* const* d_in, const int* in_sizes, int n_in,
                              void* d_out, int out_size)
{
    const float* x     = (const float*)d_in[0];   // (4,1,524288)
    const float* W_in  = (const float*)d_in[1];   // (256,128)
    const float* Wp    = (const float*)d_in[2];   // (4,256,256)
    const float* Wk    = (const float*)d_in[3];
    const float* Wv    = (const float*)d_in[4];
    const float* Wq    = (const float*)d_in[5];
    const float* W_out = (const float*)d_in[6];   // (128,256)
    float* out = (float*)d_out;                   // (4,4096,128)

    float *h, *hp, *kb, *qb, *vb, *mm;
    cudaGetSymbolAddress((void**)&h,  g_h);
    cudaGetSymbolAddress((void**)&hp, g_hp);
    cudaGetSymbolAddress((void**)&kb, g_k);
    cudaGetSymbolAddress((void**)&qb, g_q);
    cudaGetSymbolAddress((void**)&vb, g_v);
    cudaGetSymbolAddress((void**)&mm, g_m);

    const dim3 blk(256);

    // Input projection: h = blocked_x @ W_in^T   (16384 x 256, K=128)
    gemm_nt<<<dim3(CDIM/128, NBT/128), blk>>>(x, W_in, h, NBT, CDIM, 128);

    for (int l = 0; l < NLAYERS; l++) {
        const float* wp = Wp + (size_t)l * CDIM * CDIM;
        const float* wk = Wk + (size_t)l * CDIM * CDIM;
        const float* wv = Wv + (size_t)l * CDIM * CDIM;
        const float* wq = Wq + (size_t)l * CDIM * CDIM;

        // hp = h @ wp^T ; K/Q/V = hp @ {wk,wq,wv}^T   (K=256: single panel)
        gemm_nt<<<dim3(2, NBT/128), blk>>>(h,  wp, hp, NBT, CDIM, CDIM);
        gemm_nt<<<dim3(2, NBT/128), blk>>>(hp, wk, kb, NBT, CDIM, CDIM);
        gemm_nt<<<dim3(2, NBT/128), blk>>>(hp, wq, qb, NBT, CDIM, CDIM);
        gemm_nt<<<dim3(2, NBT/128), blk>>>(hp, wv, vb, NBT, CDIM, CDIM);

        // M[t,s] = k_t . q_s, tril (per batch), K=256: single panel
        scores_kernel<<<dim3(NB/128, NB/128, BATCH), blk>>>(kb, qb, mm);

        // h[s,c] = tanh( sum_t M[t,s] V[t,c] ), K=4096: kc=320 panels
        av_tanh_kernel<<<dim3(CDIM/128, NB/128, BATCH), blk>>>(mm, vb, h);
    }

    // Output projection: out = h @ W_out^T   (16384 x 128, K=256)
    gemm_nt<<<dim3(1, NBT/128), blk>>>(h, W_out, out, NBT, 128, CDIM);
}

// round 11
// speedup vs baseline: 1.2335x; 1.2249x over previous
#include <cuda_runtime.h>
#include <math.h>
#include <stdint.h>

// Problem constants
#define NBT    16384    // B * n_blocks (4 * 4096)
#define CDIM   256      // model channels
#define NB     4096     // blocks (tokens) per batch
#define BATCH  4
#define NLAYERS 4
#define KC320  320      // Eigen TensorContractionBlocking kc cap

#define BK 32           // k-slice per smem stage (320 % 32 == 0)
#define LDW (128 + 4)   // smem row width in floats (132*4B = 528B, 16B-aligned)

typedef unsigned long long u64;

// ---------------- scratch (device globals; no runtime allocation) ----------
__device__ float g_h [NBT * CDIM];
__device__ float g_hp[NBT * CDIM];
__device__ float g_k [NBT * CDIM];
__device__ float g_q [NBT * CDIM];
__device__ float g_v [NBT * CDIM];
__device__ float g_m [(size_t)BATCH * NB * NB];   // 268 MB score matrices

// ---------------------------------------------------------------------------
// f32x2 packed helpers: two INDEPENDENT IEEE RN ops per instruction ->
// bitwise identical to scalar fmaf / __fadd_rn on each half.
// ---------------------------------------------------------------------------
__device__ __forceinline__ u64 pack2(float lo, float hi)
{ u64 r; asm("mov.b64 %0, {%1,%2};" : "=l"(r) : "f"(lo), "f"(hi)); return r; }
__device__ __forceinline__ void unpack2(u64 v, float& lo, float& hi)
{ asm("mov.b64 {%0,%1}, %2;" : "=f"(lo), "=f"(hi) : "l"(v)); }
__device__ __forceinline__ u64 fma2(u64 a, u64 b, u64 c)
{ u64 d; asm("fma.rn.f32x2 %0, %1, %2, %3;" : "=l"(d) : "l"(a), "l"(b), "l"(c)); return d; }
__device__ __forceinline__ u64 add2(u64 a, u64 b)
{ u64 d; asm("add.rn.f32x2 %0, %1, %2;" : "=l"(d) : "l"(a), "l"(b)); return d; }

// ---------------------------------------------------------------------------
// XLA:CPU llvm_ir::EmitFastTanh, with_fma=true: clamp +-7.99881172180175781,
// FMA Horner, RN divide, |x|<4e-4 -> x (select on unclamped input).
// ---------------------------------------------------------------------------
__device__ __forceinline__ float tanh_xla(float x)
{
    const float kClamp = 7.99881172180175781f;
    float xc = fminf(fmaxf(x, -kClamp), kClamp);
    float x2 = xc * xc;
    float p = -2.76076847742355e-16f;
    p = fmaf(x2, p,  2.00018790482477e-13f);
    p = fmaf(x2, p, -8.60467152213735e-11f);
    p = fmaf(x2, p,  5.12229709037114e-08f);
    p = fmaf(x2, p,  1.48572235717979e-05f);
    p = fmaf(x2, p,  6.37261928875436e-04f);
    p = fmaf(x2, p,  4.89352455891786e-03f);
    p = xc * p;
    float q = 1.19825839466702e-06f;
    q = fmaf(x2, q, 1.18534705686654e-04f);
    q = fmaf(x2, q, 2.26843463243900e-03f);
    q = fmaf(x2, q, 4.89352518554385e-03f);
    float r = __fdiv_rn(p, q);
    return (fabsf(x) < 0.0004f) ? x : r;
}

// 8x8 microtile step, conflict-free mapping:
//   rows  i: (i<4 ? ty*4+i : 64+ty*4+i-4)      (A read = quarter-warp broadcast)
//   cols  j2 pairs: {tx*4, tx*4+2, 64+tx*4, 64+tx*4+2}  (B read = 16B consecutive)
// 32 FFMA2 = 64 scalar FMAs; each output keeps its single ascending chain.
#define MICRO_STEP(AsRow, BsRow)                                          \
    do {                                                                  \
        float4 alo = *(const float4*)&(AsRow)[ty << 2];                   \
        float4 ahi = *(const float4*)&(AsRow)[64 + (ty << 2)];            \
        ulonglong2 blo = *(const ulonglong2*)&(BsRow)[tx << 2];           \
        ulonglong2 bhi = *(const ulonglong2*)&(BsRow)[64 + (tx << 2)];    \
        u64 b2[4] = {blo.x, blo.y, bhi.x, bhi.y};                         \
        float am[8] = {alo.x, alo.y, alo.z, alo.w,                        \
                       ahi.x, ahi.y, ahi.z, ahi.w};                       \
        _Pragma("unroll")                                                 \
        for (int i_ = 0; i_ < 8; i_++) {                                  \
            u64 a2 = pack2(am[i_], am[i_]);                               \
            _Pragma("unroll")                                             \
            for (int j_ = 0; j_ < 4; j_++)                                \
                acc2[i_][j_] = fma2(a2, b2[j_], acc2[i_][j_]);            \
        }                                                                 \
    } while (0)

// Transposing loader for NT operands: thread loads 4 float4 along k, scatters
// to k-major smem rows. lr = tid>>2 (0..63), lk = (tid&3)*4.
#define LOAD_NT(Sm, Base, LD)                                             \
    do {                                                                  \
        _Pragma("unroll")                                                 \
        for (int rh_ = 0; rh_ < 2; rh_++)                                 \
            _Pragma("unroll")                                             \
            for (int kh_ = 0; kh_ < 2; kh_++) {                           \
                float4 v_ = *(const float4*)((Base) +                     \
                    (size_t)(lr + 64*rh_) * (LD) + k0 + lk + 16*kh_);     \
                (Sm)[lk + 16*kh_ + 0][lr + 64*rh_] = v_.x;                \
                (Sm)[lk + 16*kh_ + 1][lr + 64*rh_] = v_.y;                \
                (Sm)[lk + 16*kh_ + 2][lr + 64*rh_] = v_.z;                \
                (Sm)[lk + 16*kh_ + 3][lr + 64*rh_] = v_.w;                \
            }                                                             \
    } while (0)

// ---------------------------------------------------------------------------
// gemm_nt: C[m,n] = sum_k A[m,k] * B[n,k]   (A: MxK, B: NxK, row-major)
// 128x128 tile, 8x8 microtile, FFMA2. Single ascending chain (K <= 320).
// ---------------------------------------------------------------------------
__global__ void __launch_bounds__(256, 2)
gemm_nt(const float* __restrict__ A, const float* __restrict__ B,
        float* __restrict__ C, int M, int N, int K)
{
    __shared__ float As[BK][LDW];
    __shared__ float Bs[BK][LDW];

    const int bm = blockIdx.y << 7;
    const int bn = blockIdx.x << 7;
    const int tid = threadIdx.x;
    const int tx = tid & 15, ty = tid >> 4;
    const int lr = tid >> 2;
    const int lk = (tid & 3) << 2;

    u64 acc2[8][4];
    #pragma unroll
    for (int i = 0; i < 8; i++)
        #pragma unroll
        for (int j = 0; j < 4; j++) acc2[i][j] = 0ull;

    for (int k0 = 0; k0 < K; k0 += BK) {
        LOAD_NT(As, A + (size_t)bm * K, K);
        LOAD_NT(Bs, B + (size_t)bn * K, K);
        __syncthreads();
        #pragma unroll
        for (int kk = 0; kk < BK; kk++) MICRO_STEP(As[kk], Bs[kk]);
        __syncthreads();
    }

    #pragma unroll
    for (int i = 0; i < 8; i++) {
        int m = bm + ((i < 4) ? (ty << 2) + i : 64 + (ty << 2) + i - 4);
        ulonglong2 lo = {acc2[i][0], acc2[i][1]};
        ulonglong2 hi = {acc2[i][2], acc2[i][3]};
        *(ulonglong2*)(C + (size_t)m * N + bn + (tx << 2))      = lo;
        *(ulonglong2*)(C + (size_t)m * N + bn + 64 + (tx << 2)) = hi;
    }
}

// ---------------------------------------------------------------------------
// scores: per batch b, M[t,s] = sum_c K[t,c] * Q[s,c], masked (t<s -> 0).
// 128x128 tiles; fully-upper tiles skipped (never read downstream).
// ---------------------------------------------------------------------------
__global__ void __launch_bounds__(256, 2)
scores_kernel(const float* __restrict__ Kin, const float* __restrict__ Qin,
              float* __restrict__ Mout)
{
    const int bt = blockIdx.y << 7;   // t tile (output rows)
    const int bs = blockIdx.x << 7;   // s tile (output cols)
    if (bt + 127 < bs) return;        // fully upper triangle: unused

    const int b = blockIdx.z;
    const float* Kb = Kin + (size_t)b * NB * CDIM;
    const float* Qb = Qin + (size_t)b * NB * CDIM;
    float*       Mb = Mout + (size_t)b * NB * NB;

    __shared__ float As[BK][LDW];
    __shared__ float Bs[BK][LDW];

    const int tid = threadIdx.x;
    const int tx = tid & 15, ty = tid >> 4;
    const int lr = tid >> 2;
    const int lk = (tid & 3) << 2;

    u64 acc2[8][4];
    #pragma unroll
    for (int i = 0; i < 8; i++)
        #pragma unroll
        for (int j = 0; j < 4; j++) acc2[i][j] = 0ull;

    for (int k0 = 0; k0 < CDIM; k0 += BK) {
        LOAD_NT(As, Kb + (size_t)bt * CDIM, CDIM);
        LOAD_NT(Bs, Qb + (size_t)bs * CDIM, CDIM);
        __syncthreads();
        #pragma unroll
        for (int kk = 0; kk < BK; kk++) MICRO_STEP(As[kk], Bs[kk]);
        __syncthreads();
    }

    const bool interior = (bt >= bs + 127);   // whole tile strictly below diag
    #pragma unroll
    for (int i = 0; i < 8; i++) {
        int t = bt + ((i < 4) ? (ty << 2) + i : 64 + (ty << 2) + i - 4);
        if (interior) {
            ulonglong2 lo = {acc2[i][0], acc2[i][1]};
            ulonglong2 hi = {acc2[i][2], acc2[i][3]};
            *(ulonglong2*)(Mb + (size_t)t * NB + bs + (tx << 2))      = lo;
            *(ulonglong2*)(Mb + (size_t)t * NB + bs + 64 + (tx << 2)) = hi;
        } else {
            #pragma unroll
            for (int j = 0; j < 4; j++) {
                int s = bs + ((j < 2) ? (tx << 2) + (j << 1)
                                      : 64 + (tx << 2) + ((j - 2) << 1));
                float lo, hi; unpack2(acc2[i][j], lo, hi);
                Mb[(size_t)t * NB + s]     = (t < s)     ? 0.f : lo;
                Mb[(size_t)t * NB + s + 1] = (t < s + 1) ? 0.f : hi;
            }
        }
    }
}

// ---------------------------------------------------------------------------
// av_tanh: per batch b, H[s,c] = tanh( sum_t M[t,s] * V[t,c] ).
// Eigen kc=320 panels at ABSOLUTE t=320*j (aligned to BK=32 chunk starts).
// Panel totals live in SHARED memory (flushed only at boundaries) so the
// register footprint matches gemm_nt -> 2 CTAs/SM. Loop starts at the s-tile
// base: skipped prefix is exact zeros -> bitwise = full 0..NB Eigen chain.
// ---------------------------------------------------------------------------
__global__ void __launch_bounds__(256, 2)
av_tanh_kernel(const float* __restrict__ Min, const float* __restrict__ Vin,
               float* __restrict__ Hout)
{
    extern __shared__ char dyn[];
    float (*Ms)[LDW] = (float(*)[LDW])dyn;                       // 32x132 f
    float (*Vs)[LDW] = (float(*)[LDW])(dyn + sizeof(float)*BK*LDW);
    u64*   TotS      = (u64*)(dyn + 2*sizeof(float)*BK*LDW);     // 256x32 u64

    const int b  = blockIdx.z;
    const int bs = blockIdx.y << 7;   // s tile (output rows)
    const int bc = blockIdx.x << 7;   // c tile (output cols)

    const float* Mb = Min + (size_t)b * NB * NB;
    const float* Vb = Vin + (size_t)b * NB * CDIM;
    float*       Hb = Hout + (size_t)b * NB * CDIM;

    const int tid = threadIdx.x;
    const int tx = tid & 15, ty = tid >> 4;
    const int mr = tid >> 3;          // 0..31 (t-local row)
    const int mc = (tid & 7) << 2;    // 0,4,...,28

    u64 acc2[8][4];
    #pragma unroll
    for (int i = 0; i < 8; i++)
        #pragma unroll
        for (int j = 0; j < 4; j++) acc2[i][j] = 0ull;
    u64* mytot = TotS + (size_t)tid * 32;
    #pragma unroll
    for (int e = 0; e < 32; e++) mytot[e] = 0ull;

    for (int t0 = bs; t0 < NB; t0 += BK) {
        if ((t0 % KC320) == 0) {       // Eigen panel boundary (chunk-aligned)
            #pragma unroll
            for (int i = 0; i < 8; i++)
                #pragma unroll
                for (int j = 0; j < 4; j++) {
                    mytot[i*4 + j] = add2(mytot[i*4 + j], acc2[i][j]);
                    acc2[i][j] = 0ull;
                }
        }
        const float* Mrow = Mb + (size_t)(t0 + mr) * NB + bs;
        const float* Vrow = Vb + (size_t)(t0 + mr) * CDIM + bc;
        #pragma unroll
        for (int jj = 0; jj < 4; jj++) {
            *(float4*)&Ms[mr][mc + 32*jj] = *(const float4*)(Mrow + mc + 32*jj);
            *(float4*)&Vs[mr][mc + 32*jj] = *(const float4*)(Vrow + mc + 32*jj);
        }
        __syncthreads();
        #pragma unroll
        for (int kk = 0; kk < BK; kk++) MICRO_STEP(Ms[kk], Vs[kk]);
        __syncthreads();
    }

    #pragma unroll
    for (int i = 0; i < 8; i++) {
        int s = bs + ((i < 4) ? (ty << 2) + i : 64 + (ty << 2) + i - 4);
        #pragma unroll
        for (int j = 0; j < 4; j++) {
            int c = bc + ((j < 2) ? (tx << 2) + (j << 1)
                                  : 64 + (tx << 2) + ((j - 2) << 1));
            u64 tot = add2(mytot[i*4 + j], acc2[i][j]);
            float lo, hi; unpack2(tot, lo, hi);
            Hb[(size_t)s * CDIM + c]     = tanh_xla(lo);
            Hb[(size_t)s * CDIM + c + 1] = tanh_xla(hi);
        }
    }
}

// ---------------------------------------------------------------------------
extern "C" void kernel_launch(void* const* d_in, const int* in_sizes, int n_in,
                              void* d_out, int out_size)
{
    const float* x     = (const float*)d_in[0];   // (4,1,524288)
    const float* W_in  = (const float*)d_in[1];   // (256,128)
    const float* Wp    = (const float*)d_in[2];   // (4,256,256)
    const float* Wk    = (const float*)d_in[3];
    const float* Wv    = (const float*)d_in[4];
    const float* Wq    = (const float*)d_in[5];
    const float* W_out = (const float*)d_in[6];   // (128,256)
    float* out = (float*)d_out;                   // (4,4096,128)

    float *h, *hp, *kb, *qb, *vb, *mm;
    cudaGetSymbolAddress((void**)&h,  g_h);
    cudaGetSymbolAddress((void**)&hp, g_hp);
    cudaGetSymbolAddress((void**)&kb, g_k);
    cudaGetSymbolAddress((void**)&qb, g_q);
    cudaGetSymbolAddress((void**)&vb, g_v);
    cudaGetSymbolAddress((void**)&mm, g_m);

    const int AV_SMEM = 2 * (int)sizeof(float) * BK * LDW + 256 * 32 * 8;
    cudaFuncSetAttribute(av_tanh_kernel,
                         cudaFuncAttributeMaxDynamicSharedMemorySize, AV_SMEM);

    const dim3 blk(256);

    // Input projection: h = blocked_x @ W_in^T   (16384 x 256, K=128)
    gemm_nt<<<dim3(CDIM/128, NBT/128), blk>>>(x, W_in, h, NBT, CDIM, 128);

    for (int l = 0; l < NLAYERS; l++) {
        const float* wp = Wp + (size_t)l * CDIM * CDIM;
        const float* wk = Wk + (size_t)l * CDIM * CDIM;
        const float* wv = Wv + (size_t)l * CDIM * CDIM;
        const float* wq = Wq + (size_t)l * CDIM * CDIM;

        // hp = h @ wp^T ; K/Q/V = hp @ {wk,wq,wv}^T   (K=256: single panel)
        gemm_nt<<<dim3(2, NBT/128), blk>>>(h,  wp, hp, NBT, CDIM, CDIM);
        gemm_nt<<<dim3(2, NBT/128), blk>>>(hp, wk, kb, NBT, CDIM, CDIM);
        gemm_nt<<<dim3(2, NBT/128), blk>>>(hp, wq, qb, NBT, CDIM, CDIM);
        gemm_nt<<<dim3(2, NBT/128), blk>>>(hp, wv, vb, NBT, CDIM, CDIM);

        // M[t,s] = k_t . q_s, tril (per batch), K=256: single panel
        scores_kernel<<<dim3(NB/128, NB/128, BATCH), blk>>>(kb, qb, mm);

        // h[s,c] = tanh( sum_t M[t,s] V[t,c] ), K=4096: kc=320 panels
        av_tanh_kernel<<<dim3(CDIM/128, NB/128, BATCH), blk, AV_SMEM>>>(mm, vb, h);
    }

    // Output projection: out = h @ W_out^T   (16384 x 128, K=256)
    gemm_nt<<<dim3(1, NBT/128), blk>>>(h, W_out, out, NBT, 128, CDIM);
}

// round 13
// speedup vs baseline: 1.4122x; 1.1449x over previous
#include <cuda_runtime.h>
#include <math.h>
#include <stdint.h>

// Problem constants
#define NBT    16384    // B * n_blocks (4 * 4096)
#define CDIM   256      // model channels
#define NB     4096     // blocks (tokens) per batch
#define BATCH  4
#define NLAYERS 4
#define KC320  320      // Eigen TensorContractionBlocking kc cap
#define NPANEL 13       // ceil(4096/320)

#define BK  32          // k-slice per smem stage (320 % 32 == 0)
#define LDA 268         // duplicated-A smem row stride in floats (1072B, 16B-aligned)
#define LDB 132         // B smem row stride in floats (528B, 16B-aligned)

typedef unsigned long long u64;

// ---------------- scratch (device globals; no runtime allocation) ----------
__device__ float g_h [NBT * CDIM];
__device__ float g_hp[NBT * CDIM];
__device__ float g_k [NBT * CDIM];
__device__ float g_q [NBT * CDIM];
__device__ float g_v [NBT * CDIM];
__device__ float g_m [(size_t)BATCH * NB * NB];        // 268 MB scores
__device__ float g_pp[(size_t)NPANEL * NBT * CDIM];    // 218 MB av panel partials

// ---------------------------------------------------------------------------
// f32x2 packed helpers: two INDEPENDENT IEEE RN ops per instruction ->
// bitwise identical to scalar fmaf / __fadd_rn on each half.
// ---------------------------------------------------------------------------
__device__ __forceinline__ u64 pack2(float lo, float hi)
{ u64 r; asm("mov.b64 %0, {%1,%2};" : "=l"(r) : "f"(lo), "f"(hi)); return r; }
__device__ __forceinline__ u64 fma2(u64 a, u64 b, u64 c)
{ u64 d; asm("fma.rn.f32x2 %0, %1, %2, %3;" : "=l"(d) : "l"(a), "l"(b), "l"(c)); return d; }

// ---------------------------------------------------------------------------
// XLA:CPU llvm_ir::EmitFastTanh, with_fma=true: clamp +-7.99881172180175781,
// FMA Horner, RN divide, |x|<4e-4 -> x (select on unclamped input).
// ---------------------------------------------------------------------------
__device__ __forceinline__ float tanh_xla(float x)
{
    const float kClamp = 7.99881172180175781f;
    float xc = fminf(fmaxf(x, -kClamp), kClamp);
    float x2 = xc * xc;
    float p = -2.76076847742355e-16f;
    p = fmaf(x2, p,  2.00018790482477e-13f);
    p = fmaf(x2, p, -8.60467152213735e-11f);
    p = fmaf(x2, p,  5.12229709037114e-08f);
    p = fmaf(x2, p,  1.48572235717979e-05f);
    p = fmaf(x2, p,  6.37261928875436e-04f);
    p = fmaf(x2, p,  4.89352455891786e-03f);
    p = xc * p;
    float q = 1.19825839466702e-06f;
    q = fmaf(x2, q, 1.18534705686654e-04f);
    q = fmaf(x2, q, 2.26843463243900e-03f);
    q = fmaf(x2, q, 4.89352518554385e-03f);
    float r = __fdiv_rn(p, q);
    return (fabsf(x) < 0.0004f) ? x : r;
}

// 8x8 microtile step, duplicated-A layout: a pairs (v,v) read straight from
// smem as u64 -> NO pack movs. 6 LDS.128 + 32 FFMA2 = 64 scalar FMAs.
// Row map i: (i<4 ? ty*4+i : 64+ty*4+i-4); col pairs j: {tx*4, tx*4+2,
// 64+tx*4, 64+tx*4+2}. Each output keeps its single ascending FMA chain.
#define MICRO_STEP(A2Row, BsRow)                                          \
    do {                                                                  \
        const u64* Au_ = (const u64*)(A2Row);                             \
        ulonglong2 a01 = *(const ulonglong2*)&Au_[ty << 2];               \
        ulonglong2 a23 = *(const ulonglong2*)&Au_[(ty << 2) + 2];         \
        ulonglong2 a45 = *(const ulonglong2*)&Au_[64 + (ty << 2)];        \
        ulonglong2 a67 = *(const ulonglong2*)&Au_[64 + (ty << 2) + 2];    \
        ulonglong2 blo = *(const ulonglong2*)&(BsRow)[tx << 2];           \
        ulonglong2 bhi = *(const ulonglong2*)&(BsRow)[64 + (tx << 2)];    \
        u64 a2[8] = {a01.x, a01.y, a23.x, a23.y,                          \
                     a45.x, a45.y, a67.x, a67.y};                         \
        u64 b2[4] = {blo.x, blo.y, bhi.x, bhi.y};                         \
        _Pragma("unroll")                                                 \
        for (int i_ = 0; i_ < 8; i_++)                                    \
            _Pragma("unroll")                                             \
            for (int j_ = 0; j_ < 4; j_++)                                \
                acc2[i_][j_] = fma2(a2[i_], b2[j_], acc2[i_][j_]);        \
    } while (0)

// Transposing loaders for NT operands (lr = tid>>2 in 0..63, lk = (tid&3)*4).
// A side stores every value TWICE (u64 of (v,v)) for the duplicated layout.
// (r2_ is a FLOAT index here: float index 2*row == u64 index row.)
#define LOAD_NT_A2(Sm, Base, LD)                                          \
    do {                                                                  \
        _Pragma("unroll")                                                 \
        for (int rh_ = 0; rh_ < 2; rh_++)                                 \
            _Pragma("unroll")                                             \
            for (int kh_ = 0; kh_ < 2; kh_++) {                           \
                float4 v_ = *(const float4*)((Base) +                     \
                    (size_t)(lr + 64*rh_) * (LD) + k0 + lk + 16*kh_);     \
                int r2_ = (lr + 64*rh_) << 1;                             \
                *(u64*)&(Sm)[lk + 16*kh_ + 0][r2_] = pack2(v_.x, v_.x);   \
                *(u64*)&(Sm)[lk + 16*kh_ + 1][r2_] = pack2(v_.y, v_.y);   \
                *(u64*)&(Sm)[lk + 16*kh_ + 2][r2_] = pack2(v_.z, v_.z);   \
                *(u64*)&(Sm)[lk + 16*kh_ + 3][r2_] = pack2(v_.w, v_.w);   \
            }                                                             \
    } while (0)

#define LOAD_NT_B(Sm, Base, LD)                                           \
    do {                                                                  \
        _Pragma("unroll")                                                 \
        for (int rh_ = 0; rh_ < 2; rh_++)                                 \
            _Pragma("unroll")                                             \
            for (int kh_ = 0; kh_ < 2; kh_++) {                           \
                float4 v_ = *(const float4*)((Base) +                     \
                    (size_t)(lr + 64*rh_) * (LD) + k0 + lk + 16*kh_);     \
                int r_ = lr + 64*rh_;                                     \
                (Sm)[lk + 16*kh_ + 0][r_] = v_.x;                         \
                (Sm)[lk + 16*kh_ + 1][r_] = v_.y;                         \
                (Sm)[lk + 16*kh_ + 2][r_] = v_.z;                         \
                (Sm)[lk + 16*kh_ + 3][r_] = v_.w;                         \
            }                                                             \
    } while (0)

#define TILE_SMEM (BK * LDA * 4 + BK * LDB * 4)   // 34304 + 16896 = 51200 B

// ---------------------------------------------------------------------------
// gemm_nt: C[m,n] = sum_k A[m,k] * B[n,k]   (A: MxK, B: NxK, row-major)
// 128x128 tile, 8x8 microtile, FFMA2. Single ascending chain (K <= 320).
// ---------------------------------------------------------------------------
__global__ void __launch_bounds__(256, 2)
gemm_nt(const float* __restrict__ A, const float* __restrict__ B,
        float* __restrict__ C, int M, int N, int K)
{
    extern __shared__ char dyn[];
    float (*As2)[LDA] = (float(*)[LDA])dyn;
    float (*Bs)[LDB]  = (float(*)[LDB])(dyn + BK * LDA * 4);

    const int bm = blockIdx.y << 7;
    const int bn = blockIdx.x << 7;
    const int tid = threadIdx.x;
    const int tx = tid & 15, ty = tid >> 4;
    const int lr = tid >> 2;
    const int lk = (tid & 3) << 2;

    u64 acc2[8][4];
    #pragma unroll
    for (int i = 0; i < 8; i++)
        #pragma unroll
        for (int j = 0; j < 4; j++) acc2[i][j] = 0ull;

    for (int k0 = 0; k0 < K; k0 += BK) {
        LOAD_NT_A2(As2, A + (size_t)bm * K, K);
        LOAD_NT_B (Bs,  B + (size_t)bn * K, K);
        __syncthreads();
        #pragma unroll
        for (int kk = 0; kk < BK; kk++) MICRO_STEP(As2[kk], Bs[kk]);
        __syncthreads();
    }

    #pragma unroll
    for (int i = 0; i < 8; i++) {
        int m = bm + ((i < 4) ? (ty << 2) + i : 64 + (ty << 2) + i - 4);
        ulonglong2 lo = {acc2[i][0], acc2[i][1]};
        ulonglong2 hi = {acc2[i][2], acc2[i][3]};
        *(ulonglong2*)(C + (size_t)m * N + bn + (tx << 2))      = lo;
        *(ulonglong2*)(C + (size_t)m * N + bn + 64 + (tx << 2)) = hi;
    }
}

// ---------------------------------------------------------------------------
// scores: per batch b, M[t,s] = sum_c K[t,c] * Q[s,c], masked (t<s -> 0).
// ---------------------------------------------------------------------------
__global__ void __launch_bounds__(256, 2)
scores_kernel(const float* __restrict__ Kin, const float* __restrict__ Qin,
              float* __restrict__ Mout)
{
    const int bt = blockIdx.y << 7;   // t tile (output rows)
    const int bs = blockIdx.x << 7;   // s tile (output cols)
    if (bt + 127 < bs) return;        // fully upper triangle: unused

    extern __shared__ char dyn[];
    float (*As2)[LDA] = (float(*)[LDA])dyn;
    float (*Bs)[LDB]  = (float(*)[LDB])(dyn + BK * LDA * 4);

    const int b = blockIdx.z;
    const float* Kb = Kin + (size_t)b * NB * CDIM;
    const float* Qb = Qin + (size_t)b * NB * CDIM;
    float*       Mb = Mout + (size_t)b * NB * NB;

    const int tid = threadIdx.x;
    const int tx = tid & 15, ty = tid >> 4;
    const int lr = tid >> 2;
    const int lk = (tid & 3) << 2;

    u64 acc2[8][4];
    #pragma unroll
    for (int i = 0; i < 8; i++)
        #pragma unroll
        for (int j = 0; j < 4; j++) acc2[i][j] = 0ull;

    for (int k0 = 0; k0 < CDIM; k0 += BK) {
        LOAD_NT_A2(As2, Kb + (size_t)bt * CDIM, CDIM);
        LOAD_NT_B (Bs,  Qb + (size_t)bs * CDIM, CDIM);
        __syncthreads();
        #pragma unroll
        for (int kk = 0; kk < BK; kk++) MICRO_STEP(As2[kk], Bs[kk]);
        __syncthreads();
    }

    const bool interior = (bt >= bs + 127);   // whole tile strictly below diag
    #pragma unroll
    for (int i = 0; i < 8; i++) {
        int t = bt + ((i < 4) ? (ty << 2) + i : 64 + (ty << 2) + i - 4);
        if (interior) {
            ulonglong2 lo = {acc2[i][0], acc2[i][1]};
            ulonglong2 hi = {acc2[i][2], acc2[i][3]};
            *(ulonglong2*)(Mb + (size_t)t * NB + bs + (tx << 2))      = lo;
            *(ulonglong2*)(Mb + (size_t)t * NB + bs + 64 + (tx << 2)) = hi;
        } else {
            #pragma unroll
            for (int j = 0; j < 4; j++) {
                int s = bs + ((j < 2) ? (tx << 2) + (j << 1)
                                      : 64 + (tx << 2) + ((j - 2) << 1));
                float lo, hi;
                asm("mov.b64 {%0,%1}, %2;" : "=f"(lo), "=f"(hi) : "l"(acc2[i][j]));
                Mb[(size_t)t * NB + s]     = (t < s)     ? 0.f : lo;
                Mb[(size_t)t * NB + s + 1] = (t < s + 1) ? 0.f : hi;
            }
        }
    }
}

// ---------------------------------------------------------------------------
// av_panel: partial[j][sg][c] = sum over t in panel j (ascending FMA chain)
// of M[t,s] * V[t,c]. One CTA per (c-half, panel, s-tile, batch). The chain
// within a panel is exactly Eigen's; panels are later combined in ascending
// order by RN adds (the combine kernel), matching Eigen's C += panel sequence.
// t starts at max(panel_lo, bs): skipped prefix is exact zeros (fma no-ops).
// ---------------------------------------------------------------------------
__global__ void __launch_bounds__(256, 2)
av_panel_kernel(const float* __restrict__ Min, const float* __restrict__ Vin,
                float* __restrict__ Pp)
{
    const int jp = blockIdx.x >> 1;          // panel 0..12
    const int cc = blockIdx.x & 1;           // c half
    const int bs = blockIdx.y << 7;          // s tile base (batch-local)
    const int b  = blockIdx.z;

    const int t_lo0 = jp * KC320;
    const int t_hi  = min(t_lo0 + KC320, NB);
    const int t_lo  = max(t_lo0, bs);
    if (t_lo >= t_hi) return;                // panel entirely above: all-zero

    extern __shared__ char dyn[];
    float (*Ms2)[LDA] = (float(*)[LDA])dyn;          // M dup: u64 index == s_local
    float (*Vs)[LDB]  = (float(*)[LDB])(dyn + BK * LDA * 4);

    const int bc = cc << 7;
    const float* Mb = Min + (size_t)b * NB * NB;
    const float* Vb = Vin + (size_t)b * NB * CDIM;

    const int tid = threadIdx.x;
    const int tx = tid & 15, ty = tid >> 4;
    const int mr = tid >> 3;          // 0..31 (t-local row)
    const int mc = (tid & 7) << 2;    // 0,4,...,28

    u64 acc2[8][4];
    #pragma unroll
    for (int i = 0; i < 8; i++)
        #pragma unroll
        for (int j = 0; j < 4; j++) acc2[i][j] = 0ull;

    for (int t0 = t_lo; t0 < t_hi; t0 += BK) {
        const float* Mrow = Mb + (size_t)(t0 + mr) * NB + bs;
        const float* Vrow = Vb + (size_t)(t0 + mr) * CDIM + bc;
        u64* Mu = (u64*)Ms2[mr];
        #pragma unroll
        for (int jj = 0; jj < 4; jj++) {
            float4 mv = *(const float4*)(Mrow + mc + 32*jj);
            ulonglong2 w0 = {pack2(mv.x, mv.x), pack2(mv.y, mv.y)};
            ulonglong2 w1 = {pack2(mv.z, mv.z), pack2(mv.w, mv.w)};
            *(ulonglong2*)&Mu[mc + 32*jj]     = w0;   // u64 index == column
            *(ulonglong2*)&Mu[mc + 32*jj + 2] = w1;
            *(float4*)&Vs[mr][mc + 32*jj] = *(const float4*)(Vrow + mc + 32*jj);
        }
        __syncthreads();
        #pragma unroll
        for (int kk = 0; kk < BK; kk++) MICRO_STEP(Ms2[kk], Vs[kk]);
        __syncthreads();
    }

    float* Pj = Pp + (size_t)jp * NBT * CDIM + (size_t)b * NB * CDIM;
    #pragma unroll
    for (int i = 0; i < 8; i++) {
        int s = bs + ((i < 4) ? (ty << 2) + i : 64 + (ty << 2) + i - 4);
        ulonglong2 lo = {acc2[i][0], acc2[i][1]};
        ulonglong2 hi = {acc2[i][2], acc2[i][3]};
        *(ulonglong2*)(Pj + (size_t)s * CDIM + bc + (tx << 2))      = lo;
        *(ulonglong2*)(Pj + (size_t)s * CDIM + bc + 64 + (tx << 2)) = hi;
    }
}

// ---------------------------------------------------------------------------
// av_combine: H[sg,c] = tanh( sum_{j ascending} partial[j][sg][c] ), RN adds
// starting from 0 -- identical sequence to the R11 flush chain (rel_err 0.0).
// jmin = bs/320 skips panels that are exact zero for the whole s-tile.
// ---------------------------------------------------------------------------
__global__ void __launch_bounds__(256)
av_combine_kernel(const float* __restrict__ Pp, float* __restrict__ Hout)
{
    const int gid = blockIdx.x * 256 + threadIdx.x;    // one float4 each
    const int sg  = gid >> 6;                          // row (0..NBT-1)
    const int c4  = (gid & 63) << 2;
    const int bs  = (sg & (NB - 1)) & ~127;            // s-tile base in batch
    const int jmin = bs / KC320;

    float4 tot = {0.f, 0.f, 0.f, 0.f};
    for (int j = jmin; j < NPANEL; j++) {
        float4 p = *(const float4*)(Pp + ((size_t)j * NBT + sg) * CDIM + c4);
        tot.x = __fadd_rn(tot.x, p.x);
        tot.y = __fadd_rn(tot.y, p.y);
        tot.z = __fadd_rn(tot.z, p.z);
        tot.w = __fadd_rn(tot.w, p.w);
    }
    float4 o;
    o.x = tanh_xla(tot.x); o.y = tanh_xla(tot.y);
    o.z = tanh_xla(tot.z); o.w = tanh_xla(tot.w);
    *(float4*)(Hout + (size_t)sg * CDIM + c4) = o;
}

// ---------------------------------------------------------------------------
extern "C" void kernel_launch(void* const* d_in, const int* in_sizes, int n_in,
                              void* d_out, int out_size)
{
    const float* x     = (const float*)d_in[0];   // (4,1,524288)
    const float* W_in  = (const float*)d_in[1];   // (256,128)
    const float* Wp    = (const float*)d_in[2];   // (4,256,256)
    const float* Wk    = (const float*)d_in[3];
    const float* Wv    = (const float*)d_in[4];
    const float* Wq    = (const float*)d_in[5];
    const float* W_out = (const float*)d_in[6];   // (128,256)
    float* out = (float*)d_out;                   // (4,4096,128)

    float *h, *hp, *kb, *qb, *vb, *mm, *pp;
    cudaGetSymbolAddress((void**)&h,  g_h);
    cudaGetSymbolAddress((void**)&hp, g_hp);
    cudaGetSymbolAddress((void**)&kb, g_k);
    cudaGetSymbolAddress((void**)&qb, g_q);
    cudaGetSymbolAddress((void**)&vb, g_v);
    cudaGetSymbolAddress((void**)&mm, g_m);
    cudaGetSymbolAddress((void**)&pp, g_pp);

    static int attr_done = 0;
    if (!attr_done) {
        cudaFuncSetAttribute(gemm_nt,
            cudaFuncAttributeMaxDynamicSharedMemorySize, TILE_SMEM);
        cudaFuncSetAttribute(scores_kernel,
            cudaFuncAttributeMaxDynamicSharedMemorySize, TILE_SMEM);
        cudaFuncSetAttribute(av_panel_kernel,
            cudaFuncAttributeMaxDynamicSharedMemorySize, TILE_SMEM);
        attr_done = 1;
    }

    const dim3 blk(256);

    // Input projection: h = blocked_x @ W_in^T   (16384 x 256, K=128)
    gemm_nt<<<dim3(CDIM/128, NBT/128), blk, TILE_SMEM>>>(x, W_in, h, NBT, CDIM, 128);

    for (int l = 0; l < NLAYERS; l++) {
        const float* wp = Wp + (size_t)l * CDIM * CDIM;
        const float* wk = Wk + (size_t)l * CDIM * CDIM;
        const float* wv = Wv + (size_t)l * CDIM * CDIM;
        const float* wq = Wq + (size_t)l * CDIM * CDIM;

        // hp = h @ wp^T ; K/Q/V = hp @ {wk,wq,wv}^T   (K=256: single panel)
        gemm_nt<<<dim3(2, NBT/128), blk, TILE_SMEM>>>(h,  wp, hp, NBT, CDIM, CDIM);
        gemm_nt<<<dim3(2, NBT/128), blk, TILE_SMEM>>>(hp, wk, kb, NBT, CDIM, CDIM);
        gemm_nt<<<dim3(2, NBT/128), blk, TILE_SMEM>>>(hp, wq, qb, NBT, CDIM, CDIM);
        gemm_nt<<<dim3(2, NBT/128), blk, TILE_SMEM>>>(hp, wv, vb, NBT, CDIM, CDIM);

        // M[t,s] = k_t . q_s, tril (per batch), K=256: single panel
        scores_kernel<<<dim3(NB/128, NB/128, BATCH), blk, TILE_SMEM>>>(kb, qb, mm);

        // av panel partials (balanced grid), then ordered combine + tanh
        av_panel_kernel<<<dim3(2*NPANEL, NB/128, BATCH), blk, TILE_SMEM>>>(mm, vb, pp);
        av_combine_kernel<<<dim3(NBT*CDIM/4/256), blk>>>(pp, h);
    }

    // Output projection: out = h @ W_out^T   (16384 x 128, K=256)
    gemm_nt<<<dim3(1, NBT/128), blk, TILE_SMEM>>>(h, W_out, out, NBT, 128, CDIM);
}

// round 14
// speedup vs baseline: 1.6719x; 1.1839x over previous
#include <cuda_runtime.h>
#include <math.h>
#include <stdint.h>

// Problem constants
#define NBT    16384    // B * n_blocks (4 * 4096)
#define CDIM   256      // model channels
#define NB     4096     // blocks (tokens) per batch
#define BATCH  4
#define NLAYERS 4
#define KC320  320      // Eigen TensorContractionBlocking kc cap
#define NPANEL 13       // ceil(4096/320)

#define BK  32          // k-slice per smem stage (320 % 32 == 0)
#define LDW 132         // smem row stride in floats (528B, 16B-aligned)

typedef unsigned long long u64;

// ---------------- scratch (device globals; no runtime allocation) ----------
__device__ float g_h [NBT * CDIM];
__device__ float g_hp[NBT * CDIM];
__device__ float g_k [NBT * CDIM];
__device__ float g_q [NBT * CDIM];
__device__ float g_v [NBT * CDIM];
__device__ float g_m [(size_t)BATCH * NB * NB];        // 268 MB scores
__device__ float g_pp[(size_t)NPANEL * NBT * CDIM];    // 218 MB av panel partials

// ---------------------------------------------------------------------------
// f32x2 packed helpers: two INDEPENDENT IEEE RN ops per instruction ->
// bitwise identical to scalar fmaf / __fadd_rn on each half.
// ---------------------------------------------------------------------------
__device__ __forceinline__ u64 pack2(float lo, float hi)
{ u64 r; asm("mov.b64 %0, {%1,%2};" : "=l"(r) : "f"(lo), "f"(hi)); return r; }
__device__ __forceinline__ u64 fma2(u64 a, u64 b, u64 c)
{ u64 d; asm("fma.rn.f32x2 %0, %1, %2, %3;" : "=l"(d) : "l"(a), "l"(b), "l"(c)); return d; }

// ---------------------------------------------------------------------------
// XLA:CPU llvm_ir::EmitFastTanh, with_fma=true: clamp +-7.99881172180175781,
// FMA Horner, RN divide, |x|<4e-4 -> x (select on unclamped input).
// ---------------------------------------------------------------------------
__device__ __forceinline__ float tanh_xla(float x)
{
    const float kClamp = 7.99881172180175781f;
    float xc = fminf(fmaxf(x, -kClamp), kClamp);
    float x2 = xc * xc;
    float p = -2.76076847742355e-16f;
    p = fmaf(x2, p,  2.00018790482477e-13f);
    p = fmaf(x2, p, -8.60467152213735e-11f);
    p = fmaf(x2, p,  5.12229709037114e-08f);
    p = fmaf(x2, p,  1.48572235717979e-05f);
    p = fmaf(x2, p,  6.37261928875436e-04f);
    p = fmaf(x2, p,  4.89352455891786e-03f);
    p = xc * p;
    float q = 1.19825839466702e-06f;
    q = fmaf(x2, q, 1.18534705686654e-04f);
    q = fmaf(x2, q, 2.26843463243900e-03f);
    q = fmaf(x2, q, 4.89352518554385e-03f);
    float r = __fdiv_rn(p, q);
    return (fabsf(x) < 0.0004f) ? x : r;
}

// 8x8 microtile step (R11 form): A broadcast via 2x LDS.128 + 8 pack movs,
// B pairs via 2x LDS.128. LDS bytes/FMA balanced with the fma pipe.
// Row map i: (i<4 ? ty*4+i : 64+ty*4+i-4); col pairs j: {tx*4, tx*4+2,
// 64+tx*4, 64+tx*4+2}. Each output keeps its single ascending FMA chain.
#define MICRO_STEP(AsRow, BsRow)                                          \
    do {                                                                  \
        float4 alo = *(const float4*)&(AsRow)[ty << 2];                   \
        float4 ahi = *(const float4*)&(AsRow)[64 + (ty << 2)];            \
        ulonglong2 blo = *(const ulonglong2*)&(BsRow)[tx << 2];           \
        ulonglong2 bhi = *(const ulonglong2*)&(BsRow)[64 + (tx << 2)];    \
        u64 b2[4] = {blo.x, blo.y, bhi.x, bhi.y};                         \
        float am[8] = {alo.x, alo.y, alo.z, alo.w,                        \
                       ahi.x, ahi.y, ahi.z, ahi.w};                       \
        _Pragma("unroll")                                                 \
        for (int i_ = 0; i_ < 8; i_++) {                                  \
            u64 a2 = pack2(am[i_], am[i_]);                               \
            _Pragma("unroll")                                             \
            for (int j_ = 0; j_ < 4; j_++)                                \
                acc2[i_][j_] = fma2(a2, b2[j_], acc2[i_][j_]);            \
        }                                                                 \
    } while (0)

// Transposing loader for NT operands: thread loads 4 float4 along k, scatters
// to k-major smem rows. lr = tid>>2 (0..63), lk = (tid&3)*4.
#define LOAD_NT(Sm, Base, LD)                                             \
    do {                                                                  \
        _Pragma("unroll")                                                 \
        for (int rh_ = 0; rh_ < 2; rh_++)                                 \
            _Pragma("unroll")                                             \
            for (int kh_ = 0; kh_ < 2; kh_++) {                           \
                float4 v_ = *(const float4*)((Base) +                     \
                    (size_t)(lr + 64*rh_) * (LD) + k0 + lk + 16*kh_);     \
                int r_ = lr + 64*rh_;                                     \
                (Sm)[lk + 16*kh_ + 0][r_] = v_.x;                         \
                (Sm)[lk + 16*kh_ + 1][r_] = v_.y;                         \
                (Sm)[lk + 16*kh_ + 2][r_] = v_.z;                         \
                (Sm)[lk + 16*kh_ + 3][r_] = v_.w;                         \
            }                                                             \
    } while (0)

// ---------------------------------------------------------------------------
// gemm_nt: C[m,n] = sum_k A[m,k] * B[n,k]   (A: MxK, B: NxK, row-major)
// 128x128 tile, 8x8 microtile, FFMA2. Single ascending chain (K <= 320).
// ---------------------------------------------------------------------------
__global__ void __launch_bounds__(256, 2)
gemm_nt(const float* __restrict__ A, const float* __restrict__ B,
        float* __restrict__ C, int M, int N, int K)
{
    __shared__ float As[BK][LDW];
    __shared__ float Bs[BK][LDW];

    const int bm = blockIdx.y << 7;
    const int bn = blockIdx.x << 7;
    const int tid = threadIdx.x;
    const int tx = tid & 15, ty = tid >> 4;
    const int lr = tid >> 2;
    const int lk = (tid & 3) << 2;

    u64 acc2[8][4];
    #pragma unroll
    for (int i = 0; i < 8; i++)
        #pragma unroll
        for (int j = 0; j < 4; j++) acc2[i][j] = 0ull;

    for (int k0 = 0; k0 < K; k0 += BK) {
        LOAD_NT(As, A + (size_t)bm * K, K);
        LOAD_NT(Bs, B + (size_t)bn * K, K);
        __syncthreads();
        #pragma unroll
        for (int kk = 0; kk < BK; kk++) MICRO_STEP(As[kk], Bs[kk]);
        __syncthreads();
    }

    #pragma unroll
    for (int i = 0; i < 8; i++) {
        int m = bm + ((i < 4) ? (ty << 2) + i : 64 + (ty << 2) + i - 4);
        ulonglong2 lo = {acc2[i][0], acc2[i][1]};
        ulonglong2 hi = {acc2[i][2], acc2[i][3]};
        *(ulonglong2*)(C + (size_t)m * N + bn + (tx << 2))      = lo;
        *(ulonglong2*)(C + (size_t)m * N + bn + 64 + (tx << 2)) = hi;
    }
}

// ---------------------------------------------------------------------------
// gemm_nt_kqv: three NT GEMMs sharing input A (hp): z picks {Wk,Wq,Wv} ->
// {k,q,v}. M=NBT, N=K=CDIM fixed.
// ---------------------------------------------------------------------------
__global__ void __launch_bounds__(256, 2)
gemm_nt_kqv(const float* __restrict__ A,
            const float* __restrict__ W0, const float* __restrict__ W1,
            const float* __restrict__ W2,
            float* __restrict__ C0, float* __restrict__ C1,
            float* __restrict__ C2)
{
    const float* B = (blockIdx.z == 0) ? W0 : (blockIdx.z == 1) ? W1 : W2;
    float*       C = (blockIdx.z == 0) ? C0 : (blockIdx.z == 1) ? C1 : C2;

    __shared__ float As[BK][LDW];
    __shared__ float Bs[BK][LDW];

    const int bm = blockIdx.y << 7;
    const int bn = blockIdx.x << 7;
    const int tid = threadIdx.x;
    const int tx = tid & 15, ty = tid >> 4;
    const int lr = tid >> 2;
    const int lk = (tid & 3) << 2;

    u64 acc2[8][4];
    #pragma unroll
    for (int i = 0; i < 8; i++)
        #pragma unroll
        for (int j = 0; j < 4; j++) acc2[i][j] = 0ull;

    for (int k0 = 0; k0 < CDIM; k0 += BK) {
        LOAD_NT(As, A + (size_t)bm * CDIM, CDIM);
        LOAD_NT(Bs, B + (size_t)bn * CDIM, CDIM);
        __syncthreads();
        #pragma unroll
        for (int kk = 0; kk < BK; kk++) MICRO_STEP(As[kk], Bs[kk]);
        __syncthreads();
    }

    #pragma unroll
    for (int i = 0; i < 8; i++) {
        int m = bm + ((i < 4) ? (ty << 2) + i : 64 + (ty << 2) + i - 4);
        ulonglong2 lo = {acc2[i][0], acc2[i][1]};
        ulonglong2 hi = {acc2[i][2], acc2[i][3]};
        *(ulonglong2*)(C + (size_t)m * CDIM + bn + (tx << 2))      = lo;
        *(ulonglong2*)(C + (size_t)m * CDIM + bn + 64 + (tx << 2)) = hi;
    }
}

// ---------------------------------------------------------------------------
// scores: per batch b, M[t,s] = sum_c K[t,c] * Q[s,c], masked (t<s -> 0).
// ---------------------------------------------------------------------------
__global__ void __launch_bounds__(256, 2)
scores_kernel(const float* __restrict__ Kin, const float* __restrict__ Qin,
              float* __restrict__ Mout)
{
    const int bt = blockIdx.y << 7;   // t tile (output rows)
    const int bs = blockIdx.x << 7;   // s tile (output cols)
    if (bt + 127 < bs) return;        // fully upper triangle: unused

    __shared__ float As[BK][LDW];
    __shared__ float Bs[BK][LDW];

    const int b = blockIdx.z;
    const float* Kb = Kin + (size_t)b * NB * CDIM;
    const float* Qb = Qin + (size_t)b * NB * CDIM;
    float*       Mb = Mout + (size_t)b * NB * NB;

    const int tid = threadIdx.x;
    const int tx = tid & 15, ty = tid >> 4;
    const int lr = tid >> 2;
    const int lk = (tid & 3) << 2;

    u64 acc2[8][4];
    #pragma unroll
    for (int i = 0; i < 8; i++)
        #pragma unroll
        for (int j = 0; j < 4; j++) acc2[i][j] = 0ull;

    for (int k0 = 0; k0 < CDIM; k0 += BK) {
        LOAD_NT(As, Kb + (size_t)bt * CDIM, CDIM);
        LOAD_NT(Bs, Qb + (size_t)bs * CDIM, CDIM);
        __syncthreads();
        #pragma unroll
        for (int kk = 0; kk < BK; kk++) MICRO_STEP(As[kk], Bs[kk]);
        __syncthreads();
    }

    const bool interior = (bt >= bs + 127);   // whole tile strictly below diag
    #pragma unroll
    for (int i = 0; i < 8; i++) {
        int t = bt + ((i < 4) ? (ty << 2) + i : 64 + (ty << 2) + i - 4);
        if (interior) {
            ulonglong2 lo = {acc2[i][0], acc2[i][1]};
            ulonglong2 hi = {acc2[i][2], acc2[i][3]};
            *(ulonglong2*)(Mb + (size_t)t * NB + bs + (tx << 2))      = lo;
            *(ulonglong2*)(Mb + (size_t)t * NB + bs + 64 + (tx << 2)) = hi;
        } else {
            #pragma unroll
            for (int j = 0; j < 4; j++) {
                int s = bs + ((j < 2) ? (tx << 2) + (j << 1)
                                      : 64 + (tx << 2) + ((j - 2) << 1));
                float lo, hi;
                asm("mov.b64 {%0,%1}, %2;" : "=f"(lo), "=f"(hi) : "l"(acc2[i][j]));
                Mb[(size_t)t * NB + s]     = (t < s)     ? 0.f : lo;
                Mb[(size_t)t * NB + s + 1] = (t < s + 1) ? 0.f : hi;
            }
        }
    }
}

// ---------------------------------------------------------------------------
// av_panel: partial[j][sg][c] = sum over t in panel j (ascending FMA chain)
// of M[t,s] * V[t,c]. One CTA per (c-half, panel, s-tile, batch). M and V are
// both t-major -> straight float4 copies into smem (no transpose, no dup).
// t starts at max(panel_lo, bs): skipped prefix is exact zeros (fma no-ops).
// ---------------------------------------------------------------------------
__global__ void __launch_bounds__(256, 2)
av_panel_kernel(const float* __restrict__ Min, const float* __restrict__ Vin,
                float* __restrict__ Pp)
{
    const int jp = blockIdx.x >> 1;          // panel 0..12
    const int cc = blockIdx.x & 1;           // c half
    const int bs = blockIdx.y << 7;          // s tile base (batch-local)
    const int b  = blockIdx.z;

    const int t_lo0 = jp * KC320;
    const int t_hi  = min(t_lo0 + KC320, NB);
    const int t_lo  = max(t_lo0, bs);
    if (t_lo >= t_hi) return;                // panel entirely masked: all-zero

    __shared__ float Ms[BK][LDW];            // M[t][s-local]
    __shared__ float Vs[BK][LDW];            // V[t][c-local]

    const int bc = cc << 7;
    const float* Mb = Min + (size_t)b * NB * NB;
    const float* Vb = Vin + (size_t)b * NB * CDIM;

    const int tid = threadIdx.x;
    const int tx = tid & 15, ty = tid >> 4;
    const int mr = tid >> 3;          // 0..31 (t-local row)
    const int mc = (tid & 7) << 2;    // 0,4,...,28

    u64 acc2[8][4];
    #pragma unroll
    for (int i = 0; i < 8; i++)
        #pragma unroll
        for (int j = 0; j < 4; j++) acc2[i][j] = 0ull;

    for (int t0 = t_lo; t0 < t_hi; t0 += BK) {
        const float* Mrow = Mb + (size_t)(t0 + mr) * NB + bs;
        const float* Vrow = Vb + (size_t)(t0 + mr) * CDIM + bc;
        #pragma unroll
        for (int jj = 0; jj < 4; jj++) {
            *(float4*)&Ms[mr][mc + 32*jj] = *(const float4*)(Mrow + mc + 32*jj);
            *(float4*)&Vs[mr][mc + 32*jj] = *(const float4*)(Vrow + mc + 32*jj);
        }
        __syncthreads();
        #pragma unroll
        for (int kk = 0; kk < BK; kk++) MICRO_STEP(Ms[kk], Vs[kk]);
        __syncthreads();
    }

    float* Pj = Pp + (size_t)jp * NBT * CDIM + (size_t)b * NB * CDIM;
    #pragma unroll
    for (int i = 0; i < 8; i++) {
        int s = bs + ((i < 4) ? (ty << 2) + i : 64 + (ty << 2) + i - 4);
        ulonglong2 lo = {acc2[i][0], acc2[i][1]};
        ulonglong2 hi = {acc2[i][2], acc2[i][3]};
        *(ulonglong2*)(Pj + (size_t)s * CDIM + bc + (tx << 2))      = lo;
        *(ulonglong2*)(Pj + (size_t)s * CDIM + bc + 64 + (tx << 2)) = hi;
    }
}

// ---------------------------------------------------------------------------
// av_combine: H[sg,c] = tanh( sum_{j ascending} partial[j][sg][c] ), RN adds
// starting from 0 -- identical sequence to the R11 flush chain (rel_err 0.0).
// jmin = bs/320 skips panels that are exact zero for the whole s-tile.
// ---------------------------------------------------------------------------
__global__ void __launch_bounds__(256)
av_combine_kernel(const float* __restrict__ Pp, float* __restrict__ Hout)
{
    const int gid = blockIdx.x * 256 + threadIdx.x;    // one float4 each
    const int sg  = gid >> 6;                          // row (0..NBT-1)
    const int c4  = (gid & 63) << 2;
    const int bs  = (sg & (NB - 1)) & ~127;            // s-tile base in batch
    const int jmin = bs / KC320;

    float4 tot = {0.f, 0.f, 0.f, 0.f};
    for (int j = jmin; j < NPANEL; j++) {
        float4 p = *(const float4*)(Pp + ((size_t)j * NBT + sg) * CDIM + c4);
        tot.x = __fadd_rn(tot.x, p.x);
        tot.y = __fadd_rn(tot.y, p.y);
        tot.z = __fadd_rn(tot.z, p.z);
        tot.w = __fadd_rn(tot.w, p.w);
    }
    float4 o;
    o.x = tanh_xla(tot.x); o.y = tanh_xla(tot.y);
    o.z = tanh_xla(tot.z); o.w = tanh_xla(tot.w);
    *(float4*)(Hout + (size_t)sg * CDIM + c4) = o;
}

// ---------------------------------------------------------------------------
extern "C" void kernel_launch(void* const* d_in, const int* in_sizes, int n_in,
                              void* d_out, int out_size)
{
    const float* x     = (const float*)d_in[0];   // (4,1,524288)
    const float* W_in  = (const float*)d_in[1];   // (256,128)
    const float* Wp    = (const float*)d_in[2];   // (4,256,256)
    const float* Wk    = (const float*)d_in[3];
    const float* Wv    = (const float*)d_in[4];
    const float* Wq    = (const float*)d_in[5];
    const float* W_out = (const float*)d_in[6];   // (128,256)
    float* out = (float*)d_out;                   // (4,4096,128)

    float *h, *hp, *kb, *qb, *vb, *mm, *pp;
    cudaGetSymbolAddress((void**)&h,  g_h);
    cudaGetSymbolAddress((void**)&hp, g_hp);
    cudaGetSymbolAddress((void**)&kb, g_k);
    cudaGetSymbolAddress((void**)&qb, g_q);
    cudaGetSymbolAddress((void**)&vb, g_v);
    cudaGetSymbolAddress((void**)&mm, g_m);
    cudaGetSymbolAddress((void**)&pp, g_pp);

    const dim3 blk(256);

    // Input projection: h = blocked_x @ W_in^T   (16384 x 256, K=128)
    gemm_nt<<<dim3(CDIM/128, NBT/128), blk>>>(x, W_in, h, NBT, CDIM, 128);

    for (int l = 0; l < NLAYERS; l++) {
        const float* wp = Wp + (size_t)l * CDIM * CDIM;
        const float* wk = Wk + (size_t)l * CDIM * CDIM;
        const float* wv = Wv + (size_t)l * CDIM * CDIM;
        const float* wq = Wq + (size_t)l * CDIM * CDIM;

        // hp = h @ wp^T, then K/Q/V = hp @ {wk,wq,wv}^T in ONE batched launch
        gemm_nt<<<dim3(2, NBT/128), blk>>>(h, wp, hp, NBT, CDIM, CDIM);
        gemm_nt_kqv<<<dim3(2, NBT/128, 3), blk>>>(hp, wk, wq, wv, kb, qb, vb);

        // M[t,s] = k_t . q_s, tril (per batch), K=256: single panel
        scores_kernel<<<dim3(NB/128, NB/128, BATCH), blk>>>(kb, qb, mm);

        // av panel partials (balanced grid), then ordered combine + tanh
        av_panel_kernel<<<dim3(2*NPANEL, NB/128, BATCH), blk>>>(mm, vb, pp);
        av_combine_kernel<<<dim3(NBT*CDIM/4/256), blk>>>(pp, h);
    }

    // Output projection: out = h @ W_out^T   (16384 x 128, K=256)
    gemm_nt<<<dim3(1, NBT/128), blk>>>(h, W_out, out, NBT, 128, CDIM);
}